// round 1
// baseline (speedup 1.0000x reference)
#include <cuda_runtime.h>

#define M_ROWS 131072
#define N_VERTS 4000
#define DIMS 16
#define NPAIRS (N_VERTS / 2)          // 2000
#define SLOTS 18                      // f32x2 slots per pair: 1 x (-h) + 16 x d + 1 pad (=144B, 16B aligned)
#define TILE_PAIRS 1000
#define NTILES (NPAIRS / TILE_PAIRS)  // 2
#define BLOCK 512
#define SMEM_BYTES (TILE_PAIRS * SLOTS * 8)

// Packed verts scratch: [pair][slot] of f32x2. 2000*18*8 = 288 KB.
__device__ float2 g_packed[NPAIRS * SLOTS];

// ---------------------------------------------------------------------------
// Prep: interleave vert pairs (d-major within pair) and fold -0.5*||y||^2
// into slot 0 so the main loop's accumulator init is free.
// ---------------------------------------------------------------------------
__global__ void prep_kernel(const float* __restrict__ verts_emb) {
    int p = blockIdx.x * blockDim.x + threadIdx.x;
    if (p >= NPAIRS) return;
    const float* y0 = verts_emb + (size_t)(2 * p) * DIMS;
    const float* y1 = verts_emb + (size_t)(2 * p + 1) * DIMS;
    float h0 = 0.f, h1 = 0.f;
    float2* dst = g_packed + (size_t)p * SLOTS;
#pragma unroll
    for (int d = 0; d < DIMS; ++d) {
        float a = y0[d], b = y1[d];
        h0 += a * a;
        h1 += b * b;
        dst[1 + d] = make_float2(a, b);
    }
    dst[0]  = make_float2(-0.5f * h0, -0.5f * h1);
    dst[17] = make_float2(0.f, 0.f);  // pad
}

// ---------------------------------------------------------------------------
// Packed f32x2 helpers (FFMA2 path — only reachable via PTX fma.rn.f32x2)
// ---------------------------------------------------------------------------
__device__ __forceinline__ void fma2(unsigned long long& acc,
                                     unsigned long long a,
                                     unsigned long long b) {
    asm("fma.rn.f32x2 %0, %1, %2, %0;" : "+l"(acc) : "l"(a), "l"(b));
}

__device__ __forceinline__ unsigned long long bcast2(float v) {
    unsigned long long r;
    unsigned int u = __float_as_uint(v);
    asm("mov.b64 %0, {%1, %1};" : "=l"(r) : "r"(u));
    return r;
}

__device__ __forceinline__ void unpack2(unsigned long long v, float& lo, float& hi) {
    unsigned int l, h;
    asm("mov.b64 {%0, %1}, %2;" : "=r"(l), "=r"(h) : "l"(v));
    lo = __int_as_float(l);
    hi = __int_as_float(h);
}

// ---------------------------------------------------------------------------
// Main: one query row per thread; argmax of (x.y - 0.5*||y||^2) over all verts.
// Verts streamed through 144 KB smem tiles; strict '>' keeps earliest index
// (matches argmin first-index tie-breaking).
// ---------------------------------------------------------------------------
__global__ void __launch_bounds__(BLOCK, 1)
nn_kernel(const float* __restrict__ x,
          const float* __restrict__ colors,
          float* __restrict__ out) {
    extern __shared__ unsigned long long s[];  // TILE_PAIRS * SLOTS u64

    const int m = blockIdx.x * BLOCK + threadIdx.x;

    // Load this thread's query row, broadcast-packed (x[d], x[d]).
    unsigned long long XX[DIMS];
    {
        const float4* xr = (const float4*)(x + (size_t)m * DIMS);
#pragma unroll
        for (int i = 0; i < 4; ++i) {
            float4 v = xr[i];
            XX[4 * i + 0] = bcast2(v.x);
            XX[4 * i + 1] = bcast2(v.y);
            XX[4 * i + 2] = bcast2(v.z);
            XX[4 * i + 3] = bcast2(v.w);
        }
    }

    float best = -3.4e38f;
    int bi = 0;

    for (int t = 0; t < NTILES; ++t) {
        __syncthreads();
        {   // Cooperative tile load: gmem -> smem as float4.
            const float4* src =
                (const float4*)(g_packed + (size_t)t * TILE_PAIRS * SLOTS);
            float4* dst = (float4*)s;
            const int nv4 = TILE_PAIRS * SLOTS / 2;  // 9000
            for (int i = threadIdx.x; i < nv4; i += BLOCK) dst[i] = src[i];
        }
        __syncthreads();

        const int nbase = t * (TILE_PAIRS * 2);

#pragma unroll 1
        for (int p = 0; p < TILE_PAIRS; p += 2) {
            // Two independent n-pair dot-product chains for FMA-latency hiding.
            const ulonglong2* ppa = (const ulonglong2*)(s + (size_t)p * SLOTS);
            const ulonglong2* ppb = (const ulonglong2*)(s + (size_t)(p + 1) * SLOTS);

            ulonglong2 qa = ppa[0];
            ulonglong2 qb = ppb[0];
            unsigned long long accA = qa.x;  // (-h0, -h1)
            unsigned long long accB = qb.x;
            fma2(accA, XX[0], qa.y);         // d0
            fma2(accB, XX[0], qb.y);

#pragma unroll
            for (int j = 1; j < 8; ++j) {    // slots 2j, 2j+1 -> d(2j-1), d(2j)
                qa = ppa[j];
                qb = ppb[j];
                fma2(accA, XX[2 * j - 1], qa.x);
                fma2(accA, XX[2 * j],     qa.y);
                fma2(accB, XX[2 * j - 1], qb.x);
                fma2(accB, XX[2 * j],     qb.y);
            }
            qa = ppa[8];                     // slot16 = d15, slot17 = pad
            qb = ppb[8];
            fma2(accA, XX[15], qa.x);
            fma2(accB, XX[15], qb.x);

            float a0, a1, b0, b1;
            unpack2(accA, a0, a1);
            unpack2(accB, b0, b1);
            const int n0 = nbase + 2 * p;
            if (a0 > best) { best = a0; bi = n0; }
            if (a1 > best) { best = a1; bi = n0 + 1; }
            if (b0 > best) { best = b0; bi = n0 + 2; }
            if (b1 > best) { best = b1; bi = n0 + 3; }
        }
    }

    // Gather color of nearest vert.
    const float* c = colors + (size_t)3 * bi;
    float* o = out + (size_t)3 * m;
    o[0] = c[0];
    o[1] = c[1];
    o[2] = c[2];
}

extern "C" void kernel_launch(void* const* d_in, const int* in_sizes, int n_in,
                              void* d_out, int out_size) {
    const float* cse    = (const float*)d_in[0];  // (M,16) f32
    const float* colors = (const float*)d_in[1];  // (N,3)  f32
    const float* vemb   = (const float*)d_in[2];  // (N,16) f32
    float* out = (float*)d_out;                   // (M,3)  f32

    cudaFuncSetAttribute(nn_kernel,
                         cudaFuncAttributeMaxDynamicSharedMemorySize,
                         SMEM_BYTES);

    prep_kernel<<<(NPAIRS + 255) / 256, 256>>>(vemb);
    nn_kernel<<<M_ROWS / BLOCK, BLOCK, SMEM_BYTES>>>(cse, colors, out);
}

// round 2
// speedup vs baseline: 1.3333x; 1.3333x over previous
#include <cuda_runtime.h>

#define M_ROWS 131072
#define N_VERTS 4000
#define DIMS 16
#define NPAIRS (N_VERTS / 2)          // 2000
#define SLOTS 18                      // f32x2 slots/pair: (-h) + 16 dims + pad = 144B
#define TILE_PAIRS 1000
#define NTILES (NPAIRS / TILE_PAIRS)  // 2
#define BLOCK 512
#define QROWS 2
#define SMEM_BYTES (TILE_PAIRS * SLOTS * 8)

// Packed verts scratch: [pair][slot] of f32x2. 2000*18*8 = 288 KB.
__device__ float2 g_packed[NPAIRS * SLOTS];

__global__ void prep_kernel(const float* __restrict__ verts_emb) {
    int p = blockIdx.x * blockDim.x + threadIdx.x;
    if (p >= NPAIRS) return;
    const float* y0 = verts_emb + (size_t)(2 * p) * DIMS;
    const float* y1 = verts_emb + (size_t)(2 * p + 1) * DIMS;
    float h0 = 0.f, h1 = 0.f;
    float2* dst = g_packed + (size_t)p * SLOTS;
#pragma unroll
    for (int d = 0; d < DIMS; ++d) {
        float a = y0[d], b = y1[d];
        h0 += a * a;
        h1 += b * b;
        dst[1 + d] = make_float2(a, b);
    }
    dst[0]  = make_float2(-0.5f * h0, -0.5f * h1);
    dst[17] = make_float2(0.f, 0.f);  // pad
}

// ---- packed f32x2 helpers (FFMA2 only reachable via PTX fma.rn.f32x2) ----
__device__ __forceinline__ void fma2(unsigned long long& acc,
                                     unsigned long long a,
                                     unsigned long long b) {
    asm("fma.rn.f32x2 %0, %1, %2, %0;" : "+l"(acc) : "l"(a), "l"(b));
}
__device__ __forceinline__ unsigned long long bcast2(float v) {
    unsigned long long r;
    unsigned int u = __float_as_uint(v);
    asm("mov.b64 %0, {%1, %1};" : "=l"(r) : "r"(u));
    return r;
}
__device__ __forceinline__ void unpack2(unsigned long long v, float& lo, float& hi) {
    unsigned int l, h;
    asm("mov.b64 {%0, %1}, %2;" : "=r"(l), "=r"(h) : "l"(v));
    lo = __int_as_float(l);
    hi = __int_as_float(h);
}

// ---------------------------------------------------------------------------
// Each thread owns TWO query rows (r0, r0+512). Verts streamed through smem;
// every LDS.128 now feeds both queries (2x FMA2 per smem byte vs R1).
// argmax of (x.y - 0.5||y||^2); strict '>' keeps earliest index == argmin.
// ---------------------------------------------------------------------------
__global__ void __launch_bounds__(BLOCK, 1)
nn_kernel(const float* __restrict__ x,
          const float* __restrict__ colors,
          float* __restrict__ out) {
    extern __shared__ unsigned long long s[];

    const int r0 = blockIdx.x * (BLOCK * QROWS) + threadIdx.x;
    const int r1 = r0 + BLOCK;

    unsigned long long X0[DIMS], X1[DIMS];
    {
        const float4* a = (const float4*)(x + (size_t)r0 * DIMS);
        const float4* b = (const float4*)(x + (size_t)r1 * DIMS);
#pragma unroll
        for (int i = 0; i < 4; ++i) {
            float4 v = a[i];
            X0[4 * i + 0] = bcast2(v.x);
            X0[4 * i + 1] = bcast2(v.y);
            X0[4 * i + 2] = bcast2(v.z);
            X0[4 * i + 3] = bcast2(v.w);
        }
#pragma unroll
        for (int i = 0; i < 4; ++i) {
            float4 v = b[i];
            X1[4 * i + 0] = bcast2(v.x);
            X1[4 * i + 1] = bcast2(v.y);
            X1[4 * i + 2] = bcast2(v.z);
            X1[4 * i + 3] = bcast2(v.w);
        }
    }

    float best0 = -3.4e38f, best1 = -3.4e38f;
    int bi0 = 0, bi1 = 0;

    for (int t = 0; t < NTILES; ++t) {
        __syncthreads();
        {
            const float4* src =
                (const float4*)(g_packed + (size_t)t * TILE_PAIRS * SLOTS);
            float4* dst = (float4*)s;
            const int nv4 = TILE_PAIRS * SLOTS / 2;  // 9000
            for (int i = threadIdx.x; i < nv4; i += BLOCK) dst[i] = src[i];
        }
        __syncthreads();

        const int nbase = t * (TILE_PAIRS * 2);

#pragma unroll 1
        for (int p = 0; p < TILE_PAIRS; p += 2) {
            const ulonglong2* ppa = (const ulonglong2*)(s + (size_t)p * SLOTS);
            const ulonglong2* ppb = (const ulonglong2*)(s + (size_t)(p + 1) * SLOTS);

            // 4 independent FMA2 chains: {pairA,pairB} x {query0,query1}
            ulonglong2 qa = ppa[0];
            ulonglong2 qb = ppb[0];
            unsigned long long aA0 = qa.x, aA1 = qa.x;  // (-h) init
            unsigned long long aB0 = qb.x, aB1 = qb.x;
            fma2(aA0, X0[0], qa.y);
            fma2(aA1, X1[0], qa.y);
            fma2(aB0, X0[0], qb.y);
            fma2(aB1, X1[0], qb.y);

#pragma unroll
            for (int j = 1; j < 8; ++j) {
                qa = ppa[j];
                qb = ppb[j];
                fma2(aA0, X0[2 * j - 1], qa.x);
                fma2(aA0, X0[2 * j],     qa.y);
                fma2(aA1, X1[2 * j - 1], qa.x);
                fma2(aA1, X1[2 * j],     qa.y);
                fma2(aB0, X0[2 * j - 1], qb.x);
                fma2(aB0, X0[2 * j],     qb.y);
                fma2(aB1, X1[2 * j - 1], qb.x);
                fma2(aB1, X1[2 * j],     qb.y);
            }
            qa = ppa[8];
            qb = ppb[8];
            fma2(aA0, X0[15], qa.x);
            fma2(aA1, X1[15], qa.x);
            fma2(aB0, X0[15], qb.x);
            fma2(aB1, X1[15], qb.x);

            const int n0 = nbase + 2 * p;
            float v0, v1;
            // query 0 best-chain
            unpack2(aA0, v0, v1);
            if (v0 > best0) { best0 = v0; bi0 = n0; }
            if (v1 > best0) { best0 = v1; bi0 = n0 + 1; }
            unpack2(aB0, v0, v1);
            if (v0 > best0) { best0 = v0; bi0 = n0 + 2; }
            if (v1 > best0) { best0 = v1; bi0 = n0 + 3; }
            // query 1 best-chain (independent)
            unpack2(aA1, v0, v1);
            if (v0 > best1) { best1 = v0; bi1 = n0; }
            if (v1 > best1) { best1 = v1; bi1 = n0 + 1; }
            unpack2(aB1, v0, v1);
            if (v0 > best1) { best1 = v0; bi1 = n0 + 2; }
            if (v1 > best1) { best1 = v1; bi1 = n0 + 3; }
        }
    }

    {
        const float* c = colors + (size_t)3 * bi0;
        float* o = out + (size_t)3 * r0;
        o[0] = c[0]; o[1] = c[1]; o[2] = c[2];
    }
    {
        const float* c = colors + (size_t)3 * bi1;
        float* o = out + (size_t)3 * r1;
        o[0] = c[0]; o[1] = c[1]; o[2] = c[2];
    }
}

extern "C" void kernel_launch(void* const* d_in, const int* in_sizes, int n_in,
                              void* d_out, int out_size) {
    const float* cse    = (const float*)d_in[0];  // (M,16) f32
    const float* colors = (const float*)d_in[1];  // (N,3)  f32
    const float* vemb   = (const float*)d_in[2];  // (N,16) f32
    float* out = (float*)d_out;                   // (M,3)  f32

    cudaFuncSetAttribute(nn_kernel,
                         cudaFuncAttributeMaxDynamicSharedMemorySize,
                         SMEM_BYTES);

    prep_kernel<<<(NPAIRS + 255) / 256, 256>>>(vemb);
    nn_kernel<<<M_ROWS / (BLOCK * QROWS), BLOCK, SMEM_BYTES>>>(cse, colors, out);
}

// round 3
// speedup vs baseline: 1.4758x; 1.1069x over previous
#include <cuda_runtime.h>
#include <math_constants.h>

#define M_ROWS 131072
#define N_VERTS 4000
#define DIMS 16
#define NPAIRS (N_VERTS / 2)          // 2000
#define SLOTS 18                      // f32x2 slots/pair: (-h/2) + 16 dims + pad = 144B
#define TILE_PAIRS 1000
#define NTILES (NPAIRS / TILE_PAIRS)  // 2
#define BLOCK 512
#define QROWS 2
#define SMEM_BYTES (TILE_PAIRS * SLOTS * 8)

// Packed verts scratch: [pair][slot] of f32x2. 2000*18*8 = 288 KB.
__device__ float2 g_packed[NPAIRS * SLOTS];

__global__ void prep_kernel(const float* __restrict__ verts_emb) {
    int p = blockIdx.x * blockDim.x + threadIdx.x;
    if (p >= NPAIRS) return;
    const float* y0 = verts_emb + (size_t)(2 * p) * DIMS;
    const float* y1 = verts_emb + (size_t)(2 * p + 1) * DIMS;
    float h0 = 0.f, h1 = 0.f;
    float2* dst = g_packed + (size_t)p * SLOTS;
#pragma unroll
    for (int d = 0; d < DIMS; ++d) {
        float a = y0[d], b = y1[d];
        h0 += a * a;
        h1 += b * b;
        dst[1 + d] = make_float2(a, b);
    }
    dst[0]  = make_float2(-0.5f * h0, -0.5f * h1);
    dst[17] = make_float2(0.f, 0.f);  // pad
}

// ---- packed f32x2 helpers (FFMA2 only reachable via PTX fma.rn.f32x2) ----
__device__ __forceinline__ void fma2(unsigned long long& acc,
                                     unsigned long long a,
                                     unsigned long long b) {
    asm("fma.rn.f32x2 %0, %1, %2, %0;" : "+l"(acc) : "l"(a), "l"(b));
}
__device__ __forceinline__ unsigned long long bcast2(float v) {
    unsigned long long r;
    unsigned int u = __float_as_uint(v);
    asm("mov.b64 %0, {%1, %1};" : "=l"(r) : "r"(u));
    return r;
}
__device__ __forceinline__ void unpack2(unsigned long long v, float& lo, float& hi) {
    unsigned int l, h;
    asm("mov.b64 {%0, %1}, %2;" : "=r"(l), "=r"(h) : "l"(v));
    lo = __int_as_float(l);
    hi = __int_as_float(h);
}

// Bit-exact scalar recompute of both lane-scores of global pair gp for query xs.
// MUST mirror the main-loop FMA order exactly (d0..d15 sequential, fma.rn).
__device__ __forceinline__ void rescore_pair(int gp, const float* xs,
                                             float& s0, float& s1) {
    const float2* pp = g_packed + (size_t)gp * SLOTS;
    float a0 = pp[0].x, a1 = pp[0].y;  // (-h/2)
#pragma unroll
    for (int d = 0; d < DIMS; ++d) {
        float2 y = pp[1 + d];
        a0 = fmaf(xs[d], y.x, a0);
        a1 = fmaf(xs[d], y.y, a1);
    }
    s0 = a0;
    s1 = a1;
}

// ---------------------------------------------------------------------------
// Each thread owns two query rows (r0, r0+512). Main loop keeps only a
// running max (FMNMX chains, no predicates) + the pair-GROUP where the max
// was last improved; the exact vert index is resolved by a 4-candidate
// bit-exact recompute at the end.
// ---------------------------------------------------------------------------
__global__ void __launch_bounds__(BLOCK, 1)
nn_kernel(const float* __restrict__ x,
          const float* __restrict__ colors,
          float* __restrict__ out) {
    extern __shared__ unsigned long long s[];

    const int r0 = blockIdx.x * (BLOCK * QROWS) + threadIdx.x;
    const int r1 = r0 + BLOCK;

    unsigned long long X0[DIMS], X1[DIMS];
    {
        const float4* a = (const float4*)(x + (size_t)r0 * DIMS);
        const float4* b = (const float4*)(x + (size_t)r1 * DIMS);
#pragma unroll
        for (int i = 0; i < 4; ++i) {
            float4 v = a[i];
            X0[4 * i + 0] = bcast2(v.x);
            X0[4 * i + 1] = bcast2(v.y);
            X0[4 * i + 2] = bcast2(v.z);
            X0[4 * i + 3] = bcast2(v.w);
        }
#pragma unroll
        for (int i = 0; i < 4; ++i) {
            float4 v = b[i];
            X1[4 * i + 0] = bcast2(v.x);
            X1[4 * i + 1] = bcast2(v.y);
            X1[4 * i + 2] = bcast2(v.z);
            X1[4 * i + 3] = bcast2(v.w);
        }
    }

    float best0 = -CUDART_INF_F, best1 = -CUDART_INF_F;
    int rec0 = 0, rec1 = 0;  // global pair index (even) of winning 2-pair group

    for (int t = 0; t < NTILES; ++t) {
        __syncthreads();
        {
            const float4* src =
                (const float4*)(g_packed + (size_t)t * TILE_PAIRS * SLOTS);
            float4* dst = (float4*)s;
            const int nv4 = TILE_PAIRS * SLOTS / 2;  // 9000
            for (int i = threadIdx.x; i < nv4; i += BLOCK) dst[i] = src[i];
        }
        __syncthreads();

        const int pbase = t * TILE_PAIRS;

#pragma unroll 1
        for (int p = 0; p < TILE_PAIRS; p += 2) {
            const ulonglong2* ppa = (const ulonglong2*)(s + (size_t)p * SLOTS);
            const ulonglong2* ppb = (const ulonglong2*)(s + (size_t)(p + 1) * SLOTS);

            // Batch all 18 LDS.128 so ptxas can front-load them (hide 29-cyc lat).
            ulonglong2 qa[9], qb[9];
#pragma unroll
            for (int j = 0; j < 9; ++j) {
                qa[j] = ppa[j];
                qb[j] = ppb[j];
            }

            // 4 independent FMA2 chains: {pairA,pairB} x {query0,query1}
            unsigned long long aA0 = qa[0].x, aA1 = qa[0].x;  // (-h/2) init
            unsigned long long aB0 = qb[0].x, aB1 = qb[0].x;
            fma2(aA0, X0[0], qa[0].y);
            fma2(aA1, X1[0], qa[0].y);
            fma2(aB0, X0[0], qb[0].y);
            fma2(aB1, X1[0], qb[0].y);
#pragma unroll
            for (int j = 1; j < 8; ++j) {
                fma2(aA0, X0[2 * j - 1], qa[j].x);
                fma2(aA0, X0[2 * j],     qa[j].y);
                fma2(aA1, X1[2 * j - 1], qa[j].x);
                fma2(aA1, X1[2 * j],     qa[j].y);
                fma2(aB0, X0[2 * j - 1], qb[j].x);
                fma2(aB0, X0[2 * j],     qb[j].y);
                fma2(aB1, X1[2 * j - 1], qb[j].x);
                fma2(aB1, X1[2 * j],     qb[j].y);
            }
            fma2(aA0, X0[15], qa[8].x);
            fma2(aA1, X1[15], qa[8].x);
            fma2(aB0, X0[15], qb[8].x);
            fma2(aB1, X1[15], qb[8].x);

            const int gp = pbase + p;  // global even pair index of this group
            float l, h, l2, h2;

            // query 0: FMNMX tree, record group on strict improvement
            unpack2(aA0, l, h);
            unpack2(aB0, l2, h2);
            {
                float t0 = fmaxf(fmaxf(l, h), fmaxf(l2, h2));
                if (t0 > best0) rec0 = gp;
                best0 = fmaxf(best0, t0);
            }
            // query 1 (independent chains)
            unpack2(aA1, l, h);
            unpack2(aB1, l2, h2);
            {
                float t1 = fmaxf(fmaxf(l, h), fmaxf(l2, h2));
                if (t1 > best1) rec1 = gp;
                best1 = fmaxf(best1, t1);
            }
        }
    }

    // ---- Resolve exact vert index: bit-exact recompute of the 4 candidates
    //      in the recorded group; first match == earliest-index argmin. ----
    {
        float xs[DIMS];
        const float4* xr = (const float4*)(x + (size_t)r0 * DIMS);
#pragma unroll
        for (int i = 0; i < 4; ++i) {
            float4 v = xr[i];
            xs[4 * i + 0] = v.x; xs[4 * i + 1] = v.y;
            xs[4 * i + 2] = v.z; xs[4 * i + 3] = v.w;
        }
        float a0, a1, b0, b1;
        rescore_pair(rec0,     xs, a0, a1);
        rescore_pair(rec0 + 1, xs, b0, b1);
        int bi = 2 * rec0 + 3;
        if (b0 == best0) bi = 2 * rec0 + 2;
        if (a1 == best0) bi = 2 * rec0 + 1;
        if (a0 == best0) bi = 2 * rec0;
        const float* c = colors + (size_t)3 * bi;
        float* o = out + (size_t)3 * r0;
        o[0] = c[0]; o[1] = c[1]; o[2] = c[2];
    }
    {
        float xs[DIMS];
        const float4* xr = (const float4*)(x + (size_t)r1 * DIMS);
#pragma unroll
        for (int i = 0; i < 4; ++i) {
            float4 v = xr[i];
            xs[4 * i + 0] = v.x; xs[4 * i + 1] = v.y;
            xs[4 * i + 2] = v.z; xs[4 * i + 3] = v.w;
        }
        float a0, a1, b0, b1;
        rescore_pair(rec1,     xs, a0, a1);
        rescore_pair(rec1 + 1, xs, b0, b1);
        int bi = 2 * rec1 + 3;
        if (b0 == best1) bi = 2 * rec1 + 2;
        if (a1 == best1) bi = 2 * rec1 + 1;
        if (a0 == best1) bi = 2 * rec1;
        const float* c = colors + (size_t)3 * bi;
        float* o = out + (size_t)3 * r1;
        o[0] = c[0]; o[1] = c[1]; o[2] = c[2];
    }
}

extern "C" void kernel_launch(void* const* d_in, const int* in_sizes, int n_in,
                              void* d_out, int out_size) {
    const float* cse    = (const float*)d_in[0];  // (M,16) f32
    const float* colors = (const float*)d_in[1];  // (N,3)  f32
    const float* vemb   = (const float*)d_in[2];  // (N,16) f32
    float* out = (float*)d_out;                   // (M,3)  f32

    cudaFuncSetAttribute(nn_kernel,
                         cudaFuncAttributeMaxDynamicSharedMemorySize,
                         SMEM_BYTES);

    prep_kernel<<<(NPAIRS + 255) / 256, 256>>>(vemb);
    nn_kernel<<<M_ROWS / (BLOCK * QROWS), BLOCK, SMEM_BYTES>>>(cse, colors, out);
}